// round 4
// baseline (speedup 1.0000x reference)
#include <cuda_runtime.h>
#include <cstdint>

// Problem constants
#define BB 128
#define SS 1024
#define FF 512
#define HH 32
#define GG 128              // 4*H
#define NTOK (BB*SS)        // 131072

// Scratch (device globals: allocation-free, graph-capturable)
__device__ float g_xg[(size_t)NTOK * GG];   // 64 MB: input-side gate preacts
__device__ float g_hs[(size_t)NTOK * HH];   // 16 MB: LSTM hidden outputs

// ---------------------------------------------------------------------------
// helpers
// ---------------------------------------------------------------------------
__device__ __forceinline__ float sigf(float x) {
    return __fdividef(1.f, 1.f + __expf(-x));
}
__device__ __forceinline__ float tanhfast(float x) {
    // tanh(x) = 2*sigmoid(2x) - 1 ; saturates correctly at +-1 (inf-safe)
    return 2.f * __fdividef(1.f, 1.f + __expf(-2.f * x)) - 1.f;
}

// packed f32x2 (FFMA2) helpers — only reachable via PTX
__device__ __forceinline__ unsigned long long pk2(float lo, float hi) {
    unsigned long long r;
    asm("mov.b64 %0, {%1,%2};" : "=l"(r) : "f"(lo), "f"(hi));
    return r;
}
__device__ __forceinline__ void upk2(unsigned long long v, float& lo, float& hi) {
    asm("mov.b64 {%0,%1}, %2;" : "=f"(lo), "=f"(hi) : "l"(v));
}
__device__ __forceinline__ void fma2(unsigned long long& d, unsigned long long a,
                                     unsigned long long b) {
    asm("fma.rn.f32x2 %0, %1, %2, %0;" : "+l"(d) : "l"(a), "l"(b));
}

// ---------------------------------------------------------------------------
// K1: front MLP.  xg = (tanh(tanh(x@W1+b1)@W2+b2))@Wx + bl
// CTA: 256 threads, 64 tokens.  grid = NTOK/64 = 2048
// ---------------------------------------------------------------------------
__global__ __launch_bounds__(256) void k_front(
    const float* __restrict__ x,  const float* __restrict__ W1, const float* __restrict__ b1,
    const float* __restrict__ W2, const float* __restrict__ b2,
    const float* __restrict__ Wx, const float* __restrict__ bl)
{
    __shared__ float xs [64 * 68];   // x tile, K-chunk of 64 (stride 68: 16B-aligned rows)
    __shared__ float h1s[64 * 36];   // tanh(x@W1+b1), stride 36 (16B-aligned)
    __shared__ float h2s[64 * 68];   // tanh(h1@W2+b2)

    const int tid  = threadIdx.x;
    const int tok0 = blockIdx.x * 64;

    // ---- GEMM1: [64,512] @ [512,32] ----
    const int c  = tid & 31;     // output column 0..31
    const int r8 = tid >> 5;     // token octet 0..7
    float acc[8];
#pragma unroll
    for (int i = 0; i < 8; i++) acc[i] = 0.f;

    for (int kk = 0; kk < FF; kk += 64) {
        __syncthreads();
        // stage x chunk: 64 tokens x 64 k = 1024 float4
#pragma unroll
        for (int q = 0; q < 4; q++) {
            int idx  = tid + 256 * q;          // 0..1023
            int trow = idx >> 4;               // token 0..63
            int kq   = idx & 15;               // float4 slot
            float4 v = *(const float4*)(x + (size_t)(tok0 + trow) * FF + kk + kq * 4);
            *(float4*)(xs + trow * 68 + kq * 4) = v;
        }
        __syncthreads();
#pragma unroll 4
        for (int k = 0; k < 64; k += 4) {
            float w0 = __ldg(W1 + (kk + k + 0) * 32 + c);
            float w1 = __ldg(W1 + (kk + k + 1) * 32 + c);
            float w2 = __ldg(W1 + (kk + k + 2) * 32 + c);
            float w3 = __ldg(W1 + (kk + k + 3) * 32 + c);
#pragma unroll
            for (int i = 0; i < 8; i++) {
                float4 xv = *(const float4*)(xs + (r8 * 8 + i) * 68 + k);
                acc[i] = fmaf(xv.w, w3, fmaf(xv.z, w2, fmaf(xv.y, w1, fmaf(xv.x, w0, acc[i]))));
            }
        }
    }
    {
        float bb = __ldg(b1 + c);
#pragma unroll
        for (int i = 0; i < 8; i++)
            h1s[(r8 * 8 + i) * 36 + c] = tanhfast(acc[i] + bb);
    }
    __syncthreads();

    // ---- GEMM2: [64,32] @ [32,64] ----
    {
        const int c2 = tid & 63;
        const int rg = tid >> 6;           // 0..3, 16 tokens each
        float a2[16];
#pragma unroll
        for (int i = 0; i < 16; i++) a2[i] = 0.f;
#pragma unroll
        for (int k = 0; k < 32; k += 4) {
            float w0 = __ldg(W2 + (k + 0) * 64 + c2);
            float w1 = __ldg(W2 + (k + 1) * 64 + c2);
            float w2 = __ldg(W2 + (k + 2) * 64 + c2);
            float w3 = __ldg(W2 + (k + 3) * 64 + c2);
#pragma unroll
            for (int i = 0; i < 16; i++) {
                float4 xv = *(const float4*)(h1s + (rg * 16 + i) * 36 + k);
                a2[i] = fmaf(xv.w, w3, fmaf(xv.z, w2, fmaf(xv.y, w1, fmaf(xv.x, w0, a2[i]))));
            }
        }
        float bb = __ldg(b2 + c2);
#pragma unroll
        for (int i = 0; i < 16; i++)
            h2s[(rg * 16 + i) * 68 + c2] = tanhfast(a2[i] + bb);
    }
    __syncthreads();

    // ---- GEMM3: [64,64] @ [64,128] -> xg ----
    {
        const int c3 = tid & 127;
        const int rg = tid >> 7;           // 0..1, 32 tokens each
        float a3[32];
#pragma unroll
        for (int i = 0; i < 32; i++) a3[i] = 0.f;
#pragma unroll 4
        for (int k = 0; k < 64; k += 4) {
            float w0 = __ldg(Wx + (k + 0) * GG + c3);
            float w1 = __ldg(Wx + (k + 1) * GG + c3);
            float w2 = __ldg(Wx + (k + 2) * GG + c3);
            float w3 = __ldg(Wx + (k + 3) * GG + c3);
#pragma unroll
            for (int i = 0; i < 32; i++) {
                float4 xv = *(const float4*)(h2s + (rg * 32 + i) * 68 + k);
                a3[i] = fmaf(xv.w, w3, fmaf(xv.z, w2, fmaf(xv.y, w1, fmaf(xv.x, w0, a3[i]))));
            }
        }
        float bb = __ldg(bl + c3);
#pragma unroll
        for (int i = 0; i < 32; i++)
            g_xg[(size_t)(tok0 + rg * 32 + i) * GG + c3] = a3[i] + bb;
    }
}

// ---------------------------------------------------------------------------
// K2: LSTM scan. One warp per batch element (grid=128, block=32).
// Thread j owns hidden unit j: keeps 4 Wh gate-columns in registers (packed
// as f32x2 pairs), broadcasts h via shfl, updates (c_j, h_j).
// ---------------------------------------------------------------------------
__global__ __launch_bounds__(32) void k_lstm(const float* __restrict__ Wh)
{
    const int b = blockIdx.x;
    const int j = threadIdx.x;                 // hidden unit 0..31

    // wif[k] = (Wh[k][j], Wh[k][32+j]) ; wgo[k] = (Wh[k][64+j], Wh[k][96+j])
    unsigned long long wif[HH], wgo[HH];
#pragma unroll
    for (int k = 0; k < HH; k++) {
        const float* row = Wh + k * GG;
        wif[k] = pk2(__ldg(row + j),      __ldg(row + 32 + j));
        wgo[k] = pk2(__ldg(row + 64 + j), __ldg(row + 96 + j));
    }

    const float* xgb = g_xg + (size_t)b * SS * GG;
    float c = 0.f, h = 0.f;

    // prefetch t=0 gate preacts
    float p_i = __ldg(xgb + j), p_f = __ldg(xgb + 32 + j),
          p_g = __ldg(xgb + 64 + j), p_o = __ldg(xgb + 96 + j);

    for (int t = 0; t < SS; t++) {
        unsigned long long aif = pk2(p_i, p_f);
        unsigned long long ago = pk2(p_g, p_o);

        // prefetch next step (overlaps the recurrence compute)
        {
            int tn = (t + 1 < SS) ? (t + 1) : t;
            const float* n = xgb + (size_t)tn * GG;
            p_i = __ldg(n + j);      p_f = __ldg(n + 32 + j);
            p_g = __ldg(n + 64 + j); p_o = __ldg(n + 96 + j);
        }

#pragma unroll
        for (int k = 0; k < HH; k++) {
            float hk = __shfl_sync(0xffffffffu, h, k);
            unsigned long long hh = pk2(hk, hk);
            fma2(aif, hh, wif[k]);
            fma2(ago, hh, wgo[k]);
        }

        float ai, af, ag, ao;
        upk2(aif, ai, af);
        upk2(ago, ag, ao);

        float ig = sigf(ai), fg = sigf(af), og = sigf(ao);
        c = fg * c + ig * tanhfast(ag);
        h = og * tanhfast(c);

        g_hs[((size_t)b * SS + t) * HH + j] = h;
    }
}

// ---------------------------------------------------------------------------
// K3: back MLP.  out = tanh(hs@W3+b3) @ W4 + b4
// CTA: 256 threads, 64 tokens. grid = 2048
// ---------------------------------------------------------------------------
__global__ __launch_bounds__(256) void k_back(
    const float* __restrict__ W3, const float* __restrict__ b3,
    const float* __restrict__ W4, const float* __restrict__ b4,
    float* __restrict__ out)
{
    __shared__ float hss[64 * 36];   // hs tile
    __shared__ float h3s[64 * 68];   // tanh(hs@W3+b3)

    const int tid  = threadIdx.x;
    const int tok0 = blockIdx.x * 64;

    // stage hs tile (64x32)
#pragma unroll
    for (int i = tid; i < 64 * 32; i += 256) {
        int t = i >> 5, k = i & 31;
        hss[t * 36 + k] = g_hs[(size_t)(tok0 + t) * HH + k];
    }
    __syncthreads();

    // ---- GEMM W3: [64,32]@[32,64] ----
    {
        const int c2 = tid & 63;
        const int rg = tid >> 6;
        float a2[16];
#pragma unroll
        for (int i = 0; i < 16; i++) a2[i] = 0.f;
#pragma unroll
        for (int k = 0; k < 32; k += 4) {
            float w0 = __ldg(W3 + (k + 0) * 64 + c2);
            float w1 = __ldg(W3 + (k + 1) * 64 + c2);
            float w2 = __ldg(W3 + (k + 2) * 64 + c2);
            float w3 = __ldg(W3 + (k + 3) * 64 + c2);
#pragma unroll
            for (int i = 0; i < 16; i++) {
                float4 xv = *(const float4*)(hss + (rg * 16 + i) * 36 + k);
                a2[i] = fmaf(xv.w, w3, fmaf(xv.z, w2, fmaf(xv.y, w1, fmaf(xv.x, w0, a2[i]))));
            }
        }
        float bb = __ldg(b3 + c2);
#pragma unroll
        for (int i = 0; i < 16; i++)
            h3s[(rg * 16 + i) * 68 + c2] = tanhfast(a2[i] + bb);
    }
    __syncthreads();

    // ---- GEMM W4: [64,64]@[64,512], N-chunks of 128 ----
    const int c4 = tid & 127;
    const int rg = tid >> 7;           // 0..1, 32 tokens each
    for (int nc = 0; nc < 512; nc += 128) {
        float a4[32];
#pragma unroll
        for (int i = 0; i < 32; i++) a4[i] = 0.f;
#pragma unroll 4
        for (int k = 0; k < 64; k += 4) {
            float w0 = __ldg(W4 + (k + 0) * 512 + nc + c4);
            float w1 = __ldg(W4 + (k + 1) * 512 + nc + c4);
            float w2 = __ldg(W4 + (k + 2) * 512 + nc + c4);
            float w3 = __ldg(W4 + (k + 3) * 512 + nc + c4);
#pragma unroll
            for (int i = 0; i < 32; i++) {
                float4 xv = *(const float4*)(h3s + (rg * 32 + i) * 68 + k);
                a4[i] = fmaf(xv.w, w3, fmaf(xv.z, w2, fmaf(xv.y, w1, fmaf(xv.x, w0, a4[i]))));
            }
        }
        float bb = __ldg(b4 + nc + c4);
#pragma unroll
        for (int i = 0; i < 32; i++)
            out[(size_t)(tok0 + rg * 32 + i) * 512 + nc + c4] = a4[i] + bb;
    }
}

// ---------------------------------------------------------------------------
extern "C" void kernel_launch(void* const* d_in, const int* in_sizes, int n_in,
                              void* d_out, int out_size)
{
    const float* x  = (const float*)d_in[0];
    const float* W1 = (const float*)d_in[1];
    const float* b1 = (const float*)d_in[2];
    const float* W2 = (const float*)d_in[3];
    const float* b2 = (const float*)d_in[4];
    const float* Wx = (const float*)d_in[5];
    const float* Wh = (const float*)d_in[6];
    const float* bl = (const float*)d_in[7];
    const float* W3 = (const float*)d_in[8];
    const float* b3 = (const float*)d_in[9];
    const float* W4 = (const float*)d_in[10];
    const float* b4 = (const float*)d_in[11];
    float* out = (float*)d_out;

    k_front<<<NTOK / 64, 256>>>(x, W1, b1, W2, b2, Wx, bl);
    k_lstm <<<BB, 32>>>(Wh);
    k_back <<<NTOK / 64, 256>>>(W3, b3, W4, b4, out);
}